// round 1
// baseline (speedup 1.0000x reference)
#include <cuda_runtime.h>

#define RES   128
#define FEAT  18
#define TPB   256

__global__ __launch_bounds__(TPB)
void densegrid_trilerp_kernel(const float* __restrict__ pts,
                              const float* __restrict__ cb,
                              const float* __restrict__ T,
                              float* __restrict__ out,
                              int N)
{
    __shared__ float stage[TPB * FEAT];   // 18 KB

    const int tid = threadIdx.x;
    const int n   = blockIdx.x * TPB + tid;

    if (n < N) {
        // ---- load 4x4 transform (broadcast), invert upper-left 3x3 ----
        const float a  = __ldg(T + 0), b  = __ldg(T + 1), c  = __ldg(T + 2),  tx = __ldg(T + 3);
        const float d  = __ldg(T + 4), e  = __ldg(T + 5), f  = __ldg(T + 6),  ty = __ldg(T + 7);
        const float g  = __ldg(T + 8), h  = __ldg(T + 9), ii = __ldg(T + 10), tz = __ldg(T + 11);

        const float A =  (e * ii - f * h);
        const float B = -(d * ii - f * g);
        const float C =  (d * h  - e * g);
        const float det = a * A + b * B + c * C;
        const float rd  = 1.0f / det;

        const float m00 = (e * ii - f * h) * rd;
        const float m01 = (c * h  - b * ii) * rd;
        const float m02 = (b * f  - c * e) * rd;
        const float m10 = (f * g  - d * ii) * rd;
        const float m11 = (a * ii - c * g) * rd;
        const float m12 = (c * d  - a * f) * rd;
        const float m20 = (d * h  - e * g) * rd;
        const float m21 = (b * g  - a * h) * rd;
        const float m22 = (a * e  - b * d) * rd;

        // ---- load point, apply inverse transform ----
        const float qx = __ldg(pts + 3 * n + 0) - tx;
        const float qy = __ldg(pts + 3 * n + 1) - ty;
        const float qz = __ldg(pts + 3 * n + 2) - tz;

        float px = m00 * qx + m01 * qy + m02 * qz;
        float py = m10 * qx + m11 * qy + m12 * qz;
        float pz = m20 * qx + m21 * qy + m22 * qz;

        // ---- trilinear setup (match reference exactly) ----
        px *= (float)(RES - 1);
        py *= (float)(RES - 1);
        pz *= (float)(RES - 1);

        const float fx = floorf(px), fy = floorf(py), fz = floorf(pz);
        const float wx = px - fx,    wy = py - fy,    wz = pz - fz;

        int ix0 = (int)fx; ix0 = max(0, min(RES - 1, ix0));
        int iy0 = (int)fy; iy0 = max(0, min(RES - 1, iy0));
        int iz0 = (int)fz; iz0 = max(0, min(RES - 1, iz0));
        const int ix1 = min(ix0 + 1, RES - 1);
        const int iy1 = min(iy0 + 1, RES - 1);
        const int iz1 = min(iz0 + 1, RES - 1);

        const float wx0 = 1.0f - wx, wy0 = 1.0f - wy, wz0 = 1.0f - wz;

        // 8 corner weights
        const float w000 = wx0 * wy0 * wz0;
        const float w100 = wx  * wy0 * wz0;
        const float w010 = wx0 * wy  * wz0;
        const float w110 = wx  * wy  * wz0;
        const float w001 = wx0 * wy0 * wz;
        const float w101 = wx  * wy0 * wz;
        const float w011 = wx0 * wy  * wz;
        const float w111 = wx  * wy  * wz;

        // 8 row offsets (in floats)
        const int ry0 = iy0 * RES, ry1 = iy1 * RES;
        const int rz0 = iz0 * RES * RES, rz1 = iz1 * RES * RES;
        const int o000 = (ix0 + ry0 + rz0) * FEAT;
        const int o100 = (ix1 + ry0 + rz0) * FEAT;
        const int o010 = (ix0 + ry1 + rz0) * FEAT;
        const int o110 = (ix1 + ry1 + rz0) * FEAT;
        const int o001 = (ix0 + ry0 + rz1) * FEAT;
        const int o101 = (ix1 + ry0 + rz1) * FEAT;
        const int o011 = (ix0 + ry1 + rz1) * FEAT;
        const int o111 = (ix1 + ry1 + rz1) * FEAT;

        float2* s2 = (float2*)stage + tid * (FEAT / 2);

        #pragma unroll
        for (int k = 0; k < FEAT / 2; k++) {
            const int kk = 2 * k;
            const float2 v000 = __ldg((const float2*)(cb + o000 + kk));
            const float2 v100 = __ldg((const float2*)(cb + o100 + kk));
            const float2 v010 = __ldg((const float2*)(cb + o010 + kk));
            const float2 v110 = __ldg((const float2*)(cb + o110 + kk));
            const float2 v001 = __ldg((const float2*)(cb + o001 + kk));
            const float2 v101 = __ldg((const float2*)(cb + o101 + kk));
            const float2 v011 = __ldg((const float2*)(cb + o011 + kk));
            const float2 v111 = __ldg((const float2*)(cb + o111 + kk));

            float2 r;
            r.x = w000 * v000.x;
            r.y = w000 * v000.y;
            r.x = fmaf(w100, v100.x, r.x);  r.y = fmaf(w100, v100.y, r.y);
            r.x = fmaf(w010, v010.x, r.x);  r.y = fmaf(w010, v010.y, r.y);
            r.x = fmaf(w110, v110.x, r.x);  r.y = fmaf(w110, v110.y, r.y);
            r.x = fmaf(w001, v001.x, r.x);  r.y = fmaf(w001, v001.y, r.y);
            r.x = fmaf(w101, v101.x, r.x);  r.y = fmaf(w101, v101.y, r.y);
            r.x = fmaf(w011, v011.x, r.x);  r.y = fmaf(w011, v011.y, r.y);
            r.x = fmaf(w111, v111.x, r.x);  r.y = fmaf(w111, v111.y, r.y);

            s2[k] = r;
        }
    }

    __syncthreads();

    // ---- coalesced block output: 256*18 floats = 1152 float4 ----
    const long long blockBase = (long long)blockIdx.x * TPB * FEAT;
    const long long remain    = (long long)N * FEAT - blockBase;

    if (remain >= (long long)TPB * FEAT) {
        // full block: vectorized copy-out
        const float4* s4 = (const float4*)stage;
        float4* o4 = (float4*)(out + blockBase);
        #pragma unroll
        for (int i = tid; i < TPB * FEAT / 4; i += TPB)
            o4[i] = s4[i];
    } else if (remain > 0) {
        // partial tail block: scalar guarded copy
        float* o = out + blockBase;
        for (int i = tid; i < (int)remain; i += TPB)
            o[i] = stage[i];
    }
}

extern "C" void kernel_launch(void* const* d_in, const int* in_sizes, int n_in,
                              void* d_out, int out_size)
{
    const float* pts = (const float*)d_in[0];
    const float* cb  = (const float*)d_in[1];
    const float* T   = (const float*)d_in[2];
    float* out       = (float*)d_out;

    const int N = in_sizes[0] / 3;
    const int blocks = (N + TPB - 1) / TPB;
    densegrid_trilerp_kernel<<<blocks, TPB>>>(pts, cb, T, out, N);
}

// round 2
// speedup vs baseline: 1.3047x; 1.3047x over previous
#include <cuda_runtime.h>

#define RES   128
#define FEAT  18
#define TPB   256

__global__ __launch_bounds__(TPB)
void densegrid_trilerp_kernel(const float* __restrict__ pts,
                              const float* __restrict__ cb,
                              const float* __restrict__ T,
                              float* __restrict__ out,
                              int N)
{
    __shared__ float stage[TPB * FEAT];   // 18 KB

    const int tid = threadIdx.x;
    const int n   = blockIdx.x * TPB + tid;

    if (n < N) {
        // ---- load 4x4 transform (broadcast), invert upper-left 3x3 ----
        const float a  = __ldg(T + 0), b  = __ldg(T + 1), c  = __ldg(T + 2),  tx = __ldg(T + 3);
        const float d  = __ldg(T + 4), e  = __ldg(T + 5), f  = __ldg(T + 6),  ty = __ldg(T + 7);
        const float g  = __ldg(T + 8), h  = __ldg(T + 9), ii = __ldg(T + 10), tz = __ldg(T + 11);

        const float A =  (e * ii - f * h);
        const float B = -(d * ii - f * g);
        const float C =  (d * h  - e * g);
        const float det = a * A + b * B + c * C;
        const float rd  = 1.0f / det;

        const float m00 = (e * ii - f * h) * rd;
        const float m01 = (c * h  - b * ii) * rd;
        const float m02 = (b * f  - c * e) * rd;
        const float m10 = (f * g  - d * ii) * rd;
        const float m11 = (a * ii - c * g) * rd;
        const float m12 = (c * d  - a * f) * rd;
        const float m20 = (d * h  - e * g) * rd;
        const float m21 = (b * g  - a * h) * rd;
        const float m22 = (a * e  - b * d) * rd;

        // ---- load point (streaming: read-once), apply inverse transform ----
        const float qx = __ldcs(pts + 3 * n + 0) - tx;
        const float qy = __ldcs(pts + 3 * n + 1) - ty;
        const float qz = __ldcs(pts + 3 * n + 2) - tz;

        float px = m00 * qx + m01 * qy + m02 * qz;
        float py = m10 * qx + m11 * qy + m12 * qz;
        float pz = m20 * qx + m21 * qy + m22 * qz;

        // ---- trilinear setup (match reference exactly) ----
        px *= (float)(RES - 1);
        py *= (float)(RES - 1);
        pz *= (float)(RES - 1);

        const float fx = floorf(px), fy = floorf(py), fz = floorf(pz);
        const float wx = px - fx,    wy = py - fy,    wz = pz - fz;

        int ix0 = (int)fx; ix0 = max(0, min(RES - 1, ix0));
        int iy0 = (int)fy; iy0 = max(0, min(RES - 1, iy0));
        int iz0 = (int)fz; iz0 = max(0, min(RES - 1, iz0));
        const int ix1 = min(ix0 + 1, RES - 1);
        const int iy1 = min(iy0 + 1, RES - 1);
        const int iz1 = min(iz0 + 1, RES - 1);

        const float wx0 = 1.0f - wx, wy0 = 1.0f - wy, wz0 = 1.0f - wz;

        const float w[8] = {
            wx0 * wy0 * wz0,   // 000
            wx  * wy0 * wz0,   // 100
            wx0 * wy  * wz0,   // 010
            wx  * wy  * wz0,   // 110
            wx0 * wy0 * wz,    // 001
            wx  * wy0 * wz,    // 101
            wx0 * wy  * wz,    // 011
            wx  * wy  * wz     // 111
        };

        const int ry0 = iy0 * RES, ry1 = iy1 * RES;
        const int rz0 = iz0 * RES * RES, rz1 = iz1 * RES * RES;
        const int o[8] = {
            (ix0 + ry0 + rz0) * FEAT,
            (ix1 + ry0 + rz0) * FEAT,
            (ix0 + ry1 + rz0) * FEAT,
            (ix1 + ry1 + rz0) * FEAT,
            (ix0 + ry0 + rz1) * FEAT,
            (ix1 + ry0 + rz1) * FEAT,
            (ix0 + ry1 + rz1) * FEAT,
            (ix1 + ry1 + rz1) * FEAT
        };

        float acc[FEAT];
        #pragma unroll
        for (int j = 0; j < FEAT; j++) acc[j] = 0.0f;

        // ---- 8 corner gathers: 5x LDG.128 from 16B-aligned window each ----
        #pragma unroll
        for (int c = 0; c < 8; c++) {
            const int   oc = o[c];
            const int   al = oc & ~3;            // 16B-aligned float index below row
            const bool  lo = ((oc & 3) == 0);    // parity: row starts at window[0] or window[2]
            const float wc = w[c];

            const float4* base = (const float4*)(cb + al);
            const float4 q0 = __ldg(base + 0);
            const float4 q1 = __ldg(base + 1);
            const float4 q2 = __ldg(base + 2);
            const float4 q3 = __ldg(base + 3);
            const float4 q4 = __ldg(base + 4);

            const float r0  = q0.x, r1  = q0.y, r2  = q0.z, r3  = q0.w;
            const float r4  = q1.x, r5  = q1.y, r6  = q1.z, r7  = q1.w;
            const float r8  = q2.x, r9  = q2.y, r10 = q2.z, r11 = q2.w;
            const float r12 = q3.x, r13 = q3.y, r14 = q3.z, r15 = q3.w;
            const float r16 = q4.x, r17 = q4.y, r18 = q4.z, r19 = q4.w;

            // feature j = window[j + (lo ? 0 : 2)]
            acc[0]  = fmaf(wc, lo ? r0  : r2 , acc[0]);
            acc[1]  = fmaf(wc, lo ? r1  : r3 , acc[1]);
            acc[2]  = fmaf(wc, lo ? r2  : r4 , acc[2]);
            acc[3]  = fmaf(wc, lo ? r3  : r5 , acc[3]);
            acc[4]  = fmaf(wc, lo ? r4  : r6 , acc[4]);
            acc[5]  = fmaf(wc, lo ? r5  : r7 , acc[5]);
            acc[6]  = fmaf(wc, lo ? r6  : r8 , acc[6]);
            acc[7]  = fmaf(wc, lo ? r7  : r9 , acc[7]);
            acc[8]  = fmaf(wc, lo ? r8  : r10, acc[8]);
            acc[9]  = fmaf(wc, lo ? r9  : r11, acc[9]);
            acc[10] = fmaf(wc, lo ? r10 : r12, acc[10]);
            acc[11] = fmaf(wc, lo ? r11 : r13, acc[11]);
            acc[12] = fmaf(wc, lo ? r12 : r14, acc[12]);
            acc[13] = fmaf(wc, lo ? r13 : r15, acc[13]);
            acc[14] = fmaf(wc, lo ? r14 : r16, acc[14]);
            acc[15] = fmaf(wc, lo ? r15 : r17, acc[15]);
            acc[16] = fmaf(wc, lo ? r16 : r18, acc[16]);
            acc[17] = fmaf(wc, lo ? r17 : r19, acc[17]);
        }

        #pragma unroll
        for (int j = 0; j < FEAT; j++)
            stage[tid * FEAT + j] = acc[j];
    }

    __syncthreads();

    // ---- coalesced block output: 256*18 floats = 1152 float4, streaming ----
    const long long blockBase = (long long)blockIdx.x * TPB * FEAT;
    const long long remain    = (long long)N * FEAT - blockBase;

    if (remain >= (long long)TPB * FEAT) {
        const float4* s4 = (const float4*)stage;
        float4* o4 = (float4*)(out + blockBase);
        #pragma unroll
        for (int i = tid; i < TPB * FEAT / 4; i += TPB)
            __stcs(o4 + i, s4[i]);
    } else if (remain > 0) {
        float* op = out + blockBase;
        for (int i = tid; i < (int)remain; i += TPB)
            __stcs(op + i, stage[i]);
    }
}

extern "C" void kernel_launch(void* const* d_in, const int* in_sizes, int n_in,
                              void* d_out, int out_size)
{
    const float* pts = (const float*)d_in[0];
    const float* cb  = (const float*)d_in[1];
    const float* T   = (const float*)d_in[2];
    float* out       = (float*)d_out;

    const int N = in_sizes[0] / 3;
    const int blocks = (N + TPB - 1) / TPB;
    densegrid_trilerp_kernel<<<blocks, TPB>>>(pts, cb, T, out, N);
}